// round 14
// baseline (speedup 1.0000x reference)
#include <cuda_runtime.h>
#include <math.h>
#include <stdint.h>

// out[n][m] = -sqrt(max(||a_n||^2 + ||b_m||^2 - 2 <a_n,b_m>, 0))
// Round 14: persistent CTAs + continuous cp.async ring (pipeline never
// drains across tiles).
//  - Grid = 2 x SM count; each CTA loops over tiles with stride gridDim.
//  - 3-stage ring of K=32 chunks, prefetch distance 2 chunks; the next
//    tile's first chunks are issued while finishing the current tile, so
//    prologue stalls exist only once per CTA, not once per tile.
//  - CTA 128x128, 128 threads (4 warps, 2m x 2n), warp tile 64x64.
//  - Epilogue staged through the just-freed ring stage -> coalesced STG.128.

#define DDIM 128
#define TM   128
#define TN   128

__device__ float g_a2[8192];
__device__ float g_b2[8192];

__global__ void norms_kernel(const float* __restrict__ A,
                             const float* __restrict__ B, int N, int M) {
    int row  = blockIdx.x * 8 + (threadIdx.x >> 5);
    int lane = threadIdx.x & 31;
    const float* src;
    float* dst;
    if (row < N) { src = A + (size_t)row * DDIM; dst = g_a2 + row; }
    else {
        int r = row - N;
        if (r >= M) return;
        src = B + (size_t)r * DDIM; dst = g_b2 + r;
    }
    float4 v = reinterpret_cast<const float4*>(src)[lane];
    float s = v.x * v.x + v.y * v.y + v.z * v.z + v.w * v.w;
    #pragma unroll
    for (int o = 16; o; o >>= 1) s += __shfl_xor_sync(0xffffffffu, s, o);
    if (lane == 0) *dst = s;
}

__device__ __forceinline__ uint32_t smem_u32(const void* p) {
    uint32_t a;
    asm("{ .reg .u64 t; cvta.to.shared.u64 t, %1; cvt.u32.u64 %0, t; }"
        : "=r"(a) : "l"(p));
    return a;
}
__device__ __forceinline__ void mma_tf32(float* c, const uint32_t* a,
                                         const uint32_t* b) {
    asm volatile(
        "mma.sync.aligned.m16n8k8.row.col.f32.tf32.tf32.f32 "
        "{%0,%1,%2,%3}, {%4,%5,%6,%7}, {%8,%9}, {%0,%1,%2,%3};"
        : "+f"(c[0]), "+f"(c[1]), "+f"(c[2]), "+f"(c[3])
        : "r"(a[0]), "r"(a[1]), "r"(a[2]), "r"(a[3]), "r"(b[0]), "r"(b[1]));
}
__device__ __forceinline__ void ldsm_x4(uint32_t* r, uint32_t addr) {
    asm volatile(
        "ldmatrix.sync.aligned.m8n8.x4.shared.b16 {%0,%1,%2,%3}, [%4];"
        : "=r"(r[0]), "=r"(r[1]), "=r"(r[2]), "=r"(r[3]) : "r"(addr));
}
__device__ __forceinline__ void cp_async16(uint32_t dst, const void* src) {
    asm volatile("cp.async.cg.shared.global [%0], [%1], 16;"
                 :: "r"(dst), "l"(src));
}
#define CP_COMMIT() asm volatile("cp.async.commit_group;" ::: "memory")
#define CP_WAIT1()  asm volatile("cp.async.wait_group 1;" ::: "memory")

// FFMA-only sqrt: magic rsqrt + 2 Newton steps; 0 -> 0 (no NaN).
__device__ __forceinline__ float fast_sqrt(float x) {
    float y = __int_as_float(0x5f3759df - (__float_as_int(x) >> 1));
    float h = 0.5f * x;
    y = y * (1.5f - h * y * y);
    y = y * (1.5f - h * y * y);
    return x * y;
}

// smem: ring 3 x 8192 floats (A 128x32 @+0, B 128x32 @+4096 per stage),
// then norms (double-buffered): a2[2][128], b2[2][128].
#define RING_F      8192
#define NORM_F      24576
#define SMEM_FLOATS (NORM_F + 512)
#define SMEM_BYTES  (SMEM_FLOATS * 4)
#define STG_STRIDE  72

// chunk c of the tile at (Ag,Bg) -> ring stage base address stBase
__device__ __forceinline__ void issue_chunk(uint32_t stBase,
                                            const float4* Ag, const float4* Bg,
                                            int c, int rL, int qL) {
    uint32_t aDst = stBase;
    uint32_t bDst = stBase + 4096 * 4;
    #pragma unroll
    for (int i = 0; i < 8; i++) {
        int r = rL + i * 16;
        int idx = r * 32 + ((qL * 4) ^ ((r & 7) << 2));
        cp_async16(aDst + idx * 4, Ag + (size_t)r * 32 + c * 8 + qL);
        cp_async16(bDst + idx * 4, Bg + (size_t)r * 32 + c * 8 + qL);
    }
    CP_COMMIT();
}

__global__ __launch_bounds__(128, 2)
void dist_mma_kernel(const float* __restrict__ A, const float* __restrict__ B,
                     float* __restrict__ out, int N, int M) {
    extern __shared__ float smem[];
    const int tid  = threadIdx.x;
    const int wid  = tid >> 5;
    const int lane = tid & 31;
    const int g    = lane >> 2;
    const int tig  = lane & 3;
    const uint32_t SA = smem_u32(smem);

    const int tcols  = M / TN;            // 64
    const int ntiles = (N / TM) * tcols;  // 4096
    const int G      = gridDim.x;

    int t = blockIdx.x;
    if (t >= ntiles) return;

    // lane constants
    const int rL = tid >> 3, qL = tid & 7;         // cp.async mapping
    const int rA_l = lane & 15;
    const int dkA  = (lane >> 4) << 2;
    const int rB_l = (lane & 7) + ((lane >> 4) << 3);
    const int dkB  = ((lane >> 3) & 1) << 2;

    uint32_t aRowOff[4], bRowOff[4];
    int aXc[4], bXc[4];
    {
        const int mb = (wid & 1) * 64, nb = (wid >> 1) * 64;
        #pragma unroll
        for (int mt = 0; mt < 4; mt++) {
            int r = mb + mt * 16 + rA_l;
            aRowOff[mt] = (uint32_t)r * 128;
            aXc[mt]     = (r & 7) << 2;
        }
        #pragma unroll
        for (int q = 0; q < 4; q++) {
            int r = nb + q * 16 + rB_l;
            bRowOff[q] = 4096 * 4 + (uint32_t)r * 128;
            bXc[q]     = (r & 7) << 2;
        }
    }
    const int mb = (wid & 1) * 64, nb = (wid >> 1) * 64;

    // tile 0 setup
    int by = t / tcols, bx = t - by * tcols;
    int row0 = by * TM, col0 = bx * TN;
    const float4* Ag = reinterpret_cast<const float4*>(A + (size_t)row0 * DDIM);
    const float4* Bg = reinterpret_cast<const float4*>(B + (size_t)col0 * DDIM);
    int p  = 0;   // norm buffer parity
    int cs = 0;   // ring stage of this tile's chunk 0

    smem[NORM_F + tid]       = g_a2[row0 + tid];          // a2 buf0
    smem[NORM_F + 256 + tid] = g_b2[col0 + tid];          // b2 buf0
    issue_chunk(SA + 0 * RING_F * 4, Ag, Bg, 0, rL, qL);
    issue_chunk(SA + 1 * RING_F * 4, Ag, Bg, 1, rL, qL);

    uint32_t af[4][4];
    uint32_t bf[8][2];
    float acc[4][8][4];

    #define CHUNK_MMA(sIdx)                                                   \
        do {                                                                  \
            uint32_t stBase = SA + (uint32_t)(sIdx) * (RING_F * 4);           \
            _Pragma("unroll")                                                 \
            for (int ks = 0; ks < 4; ks++) {                                  \
                int kk = ks << 3;                                             \
                _Pragma("unroll")                                             \
                for (int mt = 0; mt < 4; mt++)                                \
                    ldsm_x4(af[mt], stBase + aRowOff[mt] +                    \
                            ((((kk | dkA) ^ aXc[mt])) << 2));                 \
                _Pragma("unroll")                                             \
                for (int q = 0; q < 4; q++) {                                 \
                    uint32_t tt[4];                                           \
                    ldsm_x4(tt, stBase + bRowOff[q] +                         \
                            ((((kk | dkB) ^ bXc[q])) << 2));                  \
                    bf[q * 2 + 0][0] = tt[0];                                 \
                    bf[q * 2 + 0][1] = tt[1];                                 \
                    bf[q * 2 + 1][0] = tt[2];                                 \
                    bf[q * 2 + 1][1] = tt[3];                                 \
                }                                                             \
                _Pragma("unroll")                                             \
                for (int mt = 0; mt < 4; mt++)                                \
                    _Pragma("unroll")                                         \
                    for (int nt = 0; nt < 8; nt++)                            \
                        mma_tf32(acc[mt][nt], af[mt], bf[nt]);                \
            }                                                                 \
        } while (0)

    #pragma unroll 1
    while (true) {
        #pragma unroll
        for (int mt = 0; mt < 4; mt++)
            #pragma unroll
            for (int nt = 0; nt < 8; nt++)
                #pragma unroll
                for (int e = 0; e < 4; e++) acc[mt][nt][e] = 0.0f;

        const int cs1 = (cs + 1) % 3, cs2 = (cs + 2) % 3;
        const int tn = t + G;
        const bool hn = tn < ntiles;
        int nrow0 = 0, ncol0 = 0;
        const float4 *nAg = Ag, *nBg = Bg;
        if (hn) {
            int nby = tn / tcols, nbx = tn - nby * tcols;
            nrow0 = nby * TM; ncol0 = nbx * TN;
            nAg = reinterpret_cast<const float4*>(A + (size_t)nrow0 * DDIM);
            nBg = reinterpret_cast<const float4*>(B + (size_t)ncol0 * DDIM);
        }

        // c=0: consume chunk0 @cs, issue cur chunk2 -> cs2
        CP_WAIT1(); __syncthreads();
        issue_chunk(SA + (uint32_t)cs2 * (RING_F * 4), Ag, Bg, 2, rL, qL);
        CHUNK_MMA(cs);
        // c=1: consume chunk1 @cs1, issue cur chunk3 -> cs
        CP_WAIT1(); __syncthreads();
        issue_chunk(SA + (uint32_t)cs * (RING_F * 4), Ag, Bg, 3, rL, qL);
        CHUNK_MMA(cs1);
        // c=2: consume chunk2 @cs2, issue next chunk0 -> cs1 (+ next norms)
        CP_WAIT1(); __syncthreads();
        if (hn) {
            issue_chunk(SA + (uint32_t)cs1 * (RING_F * 4), nAg, nBg, 0, rL, qL);
            smem[NORM_F + (p ^ 1) * 128 + tid]       = g_a2[nrow0 + tid];
            smem[NORM_F + 256 + (p ^ 1) * 128 + tid] = g_b2[ncol0 + tid];
        } else CP_COMMIT();
        CHUNK_MMA(cs2);
        // c=3: consume chunk3 @cs, issue next chunk1 -> cs2
        CP_WAIT1(); __syncthreads();
        if (hn) issue_chunk(SA + (uint32_t)cs2 * (RING_F * 4), nAg, nBg, 1, rL, qL);
        else CP_COMMIT();
        CHUNK_MMA(cs);

        // ---- epilogue: stage transpose in just-freed ring stage cs ----
        __syncthreads();           // all warps done reading stage cs
        {
            const float* a2s = smem + NORM_F + p * 128;
            const float* b2s = smem + NORM_F + 256 + p * 128;
            float* stg = smem + cs * RING_F + wid * (16 * STG_STRIDE);

            const int cl   = 4 * (lane & 15);
            const int rsel = lane >> 4;
            const float4 b2v = *reinterpret_cast<const float4*>(&b2s[nb + cl]);
            const int xw = ((g >> 2) & 1) << 2;

            #pragma unroll
            for (int mt = 0; mt < 4; mt++) {
                #pragma unroll
                for (int nt = 0; nt < 8; nt++) {
                    int c = (nt * 8 + 2 * tig) ^ xw;
                    *reinterpret_cast<float2*>(&stg[g * STG_STRIDE + c]) =
                        make_float2(acc[mt][nt][0], acc[mt][nt][1]);
                    *reinterpret_cast<float2*>(&stg[(g + 8) * STG_STRIDE + c]) =
                        make_float2(acc[mt][nt][2], acc[mt][nt][3]);
                }
                __syncwarp();
                #pragma unroll
                for (int rr = 0; rr < 8; rr++) {
                    int r = rr * 2 + rsel;
                    int xorv = ((r >> 2) & 1) << 2;
                    float4 v = *reinterpret_cast<const float4*>(
                        &stg[r * STG_STRIDE + (cl ^ xorv)]);
                    float a2r = a2s[mb + mt * 16 + r];
                    float4 o;
                    o.x = -fast_sqrt(fmaxf(fmaf(-2.0f, v.x, a2r + b2v.x), 0.0f));
                    o.y = -fast_sqrt(fmaxf(fmaf(-2.0f, v.y, a2r + b2v.y), 0.0f));
                    o.z = -fast_sqrt(fmaxf(fmaf(-2.0f, v.z, a2r + b2v.z), 0.0f));
                    o.w = -fast_sqrt(fmaxf(fmaf(-2.0f, v.w, a2r + b2v.w), 0.0f));
                    *reinterpret_cast<float4*>(
                        &out[(size_t)(row0 + mb + mt * 16 + r) * M +
                             (col0 + nb + cl)]) = o;
                }
                __syncwarp();
            }
        }

        if (!hn) break;
        t = tn; row0 = nrow0; col0 = ncol0; Ag = nAg; Bg = nBg;
        cs = cs1; p ^= 1;
    }
    #undef CHUNK_MMA
}

extern "C" void kernel_launch(void* const* d_in, const int* in_sizes, int n_in,
                              void* d_out, int out_size) {
    const float* A = (const float*)d_in[0];   // z_anc [N,128]
    const float* B = (const float*)d_in[1];   // z_pos_neg [M,128]
    float* out = (float*)d_out;

    const int N = in_sizes[0] / DDIM;
    const int M = in_sizes[1] / DDIM;

    // One-time (pre-capture, on the correctness call): attribute + SM count.
    static int G = [] {
        cudaFuncSetAttribute(dist_mma_kernel,
                             cudaFuncAttributeMaxDynamicSharedMemorySize,
                             SMEM_BYTES);
        int dev = 0;
        cudaGetDevice(&dev);
        cudaDeviceProp prop;
        cudaGetDeviceProperties(&prop, dev);
        return prop.multiProcessorCount * 2;   // 2 CTAs/SM, persistent
    }();

    int totalRows = N + M;
    norms_kernel<<<(totalRows + 7) / 8, 256>>>(A, B, N, M);

    int ntiles = (N / TM) * (M / TN);
    int grid = G < ntiles ? G : ntiles;
    dist_mma_kernel<<<grid, 128, SMEM_BYTES>>>(A, B, out, N, M);
}

// round 15
// speedup vs baseline: 1.4220x; 1.4220x over previous
#include <cuda_runtime.h>
#include <cuda_bf16.h>
#include <math.h>
#include <stdint.h>

// out[n][m] = -sqrt(max(||a_n||^2 + ||b_m||^2 - 2 <a_n,b_m>, 0))
// Round 15: bf16 m16n8k16 mma (2x tensor rate of tf32, half the bytes).
//  - Pre-pass converts A,B fp32 -> bf16 scratch + computes fp32 norms.
//  - CTA 128x128, 256 thr (8 warps, 4m x 2n), warp tile 32x64.
//  - Whole K=128 resident: A,B bf16 tiles = 64KB -> 2 CTAs/SM, no ring.
//  - cp.async tile load; granule-XOR swizzle (256B rows, 16B granules).
//  - Epilogue staged through conflict-free smem -> coalesced STG.128.

#define DDIM 128
#define TM   128
#define TN   128

__device__ float g_a2[8192];
__device__ float g_b2[8192];
__device__ __nv_bfloat16 g_Abf[8192 * 128];
__device__ __nv_bfloat16 g_Bbf[8192 * 128];

// One warp per row: fp32 norm + bf16 conversion.
__global__ void prep_kernel(const float* __restrict__ A,
                            const float* __restrict__ B, int N, int M) {
    int row  = blockIdx.x * 8 + (threadIdx.x >> 5);
    int lane = threadIdx.x & 31;
    const float* src;
    float* dst;
    __nv_bfloat16* bdst;
    if (row < N) {
        src = A + (size_t)row * DDIM; dst = g_a2 + row;
        bdst = g_Abf + (size_t)row * DDIM;
    } else {
        int r = row - N;
        if (r >= M) return;
        src = B + (size_t)r * DDIM; dst = g_b2 + r;
        bdst = g_Bbf + (size_t)r * DDIM;
    }
    float4 v = reinterpret_cast<const float4*>(src)[lane];
    __nv_bfloat162 p0 = __float22bfloat162_rn(make_float2(v.x, v.y));
    __nv_bfloat162 p1 = __float22bfloat162_rn(make_float2(v.z, v.w));
    reinterpret_cast<__nv_bfloat162*>(bdst)[lane * 2]     = p0;
    reinterpret_cast<__nv_bfloat162*>(bdst)[lane * 2 + 1] = p1;
    float s = v.x * v.x + v.y * v.y + v.z * v.z + v.w * v.w;
    #pragma unroll
    for (int o = 16; o; o >>= 1) s += __shfl_xor_sync(0xffffffffu, s, o);
    if (lane == 0) *dst = s;
}

__device__ __forceinline__ uint32_t smem_u32(const void* p) {
    uint32_t a;
    asm("{ .reg .u64 t; cvta.to.shared.u64 t, %1; cvt.u32.u64 %0, t; }"
        : "=r"(a) : "l"(p));
    return a;
}
__device__ __forceinline__ void mma_bf16(float* c, const uint32_t* a,
                                         const uint32_t* b) {
    asm volatile(
        "mma.sync.aligned.m16n8k16.row.col.f32.bf16.bf16.f32 "
        "{%0,%1,%2,%3}, {%4,%5,%6,%7}, {%8,%9}, {%0,%1,%2,%3};"
        : "+f"(c[0]), "+f"(c[1]), "+f"(c[2]), "+f"(c[3])
        : "r"(a[0]), "r"(a[1]), "r"(a[2]), "r"(a[3]), "r"(b[0]), "r"(b[1]));
}
__device__ __forceinline__ void ldsm_x4(uint32_t* r, uint32_t addr) {
    asm volatile(
        "ldmatrix.sync.aligned.m8n8.x4.shared.b16 {%0,%1,%2,%3}, [%4];"
        : "=r"(r[0]), "=r"(r[1]), "=r"(r[2]), "=r"(r[3]) : "r"(addr));
}
__device__ __forceinline__ void cp_async16(uint32_t dst, const void* src) {
    asm volatile("cp.async.cg.shared.global [%0], [%1], 16;"
                 :: "r"(dst), "l"(src));
}
#define CP_COMMIT() asm volatile("cp.async.commit_group;" ::: "memory")
#define CP_WAIT0()  asm volatile("cp.async.wait_group 0;" ::: "memory")

// FFMA-only sqrt: magic rsqrt + 2 Newton steps; 0 -> 0 (no NaN).
__device__ __forceinline__ float fast_sqrt(float x) {
    float y = __int_as_float(0x5f3759df - (__float_as_int(x) >> 1));
    float h = 0.5f * x;
    y = y * (1.5f - h * y * y);
    y = y * (1.5f - h * y * y);
    return x * y;
}

// smem (floats): Abf tile 32KB = 8192 | Bbf tile 32KB = 8192 | a2s 128 | b2s 128
// Epilogue staging (9216 floats) reuses the tile region.
#define AS_F    0
#define BS_F    8192
#define A2S_F   16384
#define B2S_F   16512
#define SMEM_FLOATS 16640
#define SMEM_BYTES  (SMEM_FLOATS * 4)
#define STG_STRIDE  72

__global__ __launch_bounds__(256, 2)
void dist_mma_kernel(float* __restrict__ out, int N, int M) {
    extern __shared__ float smem[];
    float* a2s = smem + A2S_F;
    float* b2s = smem + B2S_F;

    const int tid  = threadIdx.x;
    const int wid  = tid >> 5;      // 0..7
    const int lane = tid & 31;
    const int g    = lane >> 2;
    const int tig  = lane & 3;
    const int row0 = blockIdx.y * TM;
    const int col0 = blockIdx.x * TN;

    const uint32_t SA = smem_u32(smem);
    const uint32_t AsA = SA;                 // bf16 A tile base
    const uint32_t BsA = SA + BS_F * 4;      // bf16 B tile base

    if (tid < 128)      a2s[tid] = g_a2[row0 + tid];
    else                b2s[tid - 128] = g_b2[col0 + tid - 128];

    // ---- cp.async whole tiles: row r (256B), granule t (16B = 8 bf16) ----
    // dst granule swizzle: t' = t ^ (r & 7)
    const __nv_bfloat16* Agb = g_Abf + (size_t)row0 * DDIM;
    const __nv_bfloat16* Bgb = g_Bbf + (size_t)col0 * DDIM;
    #pragma unroll
    for (int i = 0; i < 8; i++) {
        int f = tid + i * 256;          // 0..2047 granules
        int r = f >> 4, t = f & 15;
        uint32_t off = (uint32_t)r * 256 + (uint32_t)((t ^ (r & 7)) << 4);
        cp_async16(AsA + off, Agb + (size_t)r * DDIM + t * 8);
        cp_async16(BsA + off, Bgb + (size_t)r * DDIM + t * 8);
    }
    CP_COMMIT();
    CP_WAIT0();
    __syncthreads();

    // ---- warp tiling: 4(m) x 2(n); warp tile 32x64; k-step = 16 ----
    const int mb = (wid & 3) * 32;
    const int nb = (wid >> 2) * 64;

    // ldmatrix lane mappings (granule-space):
    // A x4 per mt: lanes 0-15 rows 0..15 @ t+0; lanes 16-31 same rows @ t+1.
    const int rA_l = lane & 15;
    const int dtA  = lane >> 4;          // 0 or 1 (granule within k-step)
    // B x4 per q: lanes 0-7 n-rows 0-7 @t+0; 8-15 @t+1; 16-23 rows 8-15 @t+0;
    //             24-31 rows 8-15 @t+1.
    const int rB_l = (lane & 7) + ((lane >> 4) << 3);
    const int dtB  = (lane >> 3) & 1;

    uint32_t aBase[2], bBase[4];
    int aXc[2], bXc[4];
    #pragma unroll
    for (int mt = 0; mt < 2; mt++) {
        int r = mb + mt * 16 + rA_l;
        aBase[mt] = AsA + (uint32_t)r * 256;
        aXc[mt]   = r & 7;
    }
    #pragma unroll
    for (int q = 0; q < 4; q++) {
        int r = nb + q * 16 + rB_l;
        bBase[q] = BsA + (uint32_t)r * 256;
        bXc[q]   = r & 7;
    }

    float acc[2][8][4];
    #pragma unroll
    for (int mt = 0; mt < 2; mt++)
        #pragma unroll
        for (int nt = 0; nt < 8; nt++)
            #pragma unroll
            for (int e = 0; e < 4; e++) acc[mt][nt][e] = 0.0f;

    uint32_t af[2][4];
    uint32_t bf[8][2];

    #pragma unroll
    for (int ks = 0; ks < 8; ks++) {
        int tk = ks * 2;
        #pragma unroll
        for (int mt = 0; mt < 2; mt++)
            ldsm_x4(af[mt], aBase[mt] + (((tk + dtA) ^ aXc[mt]) << 4));
        #pragma unroll
        for (int q = 0; q < 4; q++) {
            uint32_t t4[4];
            ldsm_x4(t4, bBase[q] + (((tk + dtB) ^ bXc[q]) << 4));
            bf[q * 2 + 0][0] = t4[0];
            bf[q * 2 + 0][1] = t4[1];
            bf[q * 2 + 1][0] = t4[2];
            bf[q * 2 + 1][1] = t4[3];
        }
        #pragma unroll
        for (int mt = 0; mt < 2; mt++)
            #pragma unroll
            for (int nt = 0; nt < 8; nt++)
                mma_bf16(acc[mt][nt], af[mt], bf[nt]);
    }

    // ---- epilogue: stage -> conflict-free smem -> coalesced STG.128 ----
    __syncthreads();               // done with tiles; reuse as staging
    float* stg = smem + wid * (16 * STG_STRIDE);

    const int cl   = 4 * (lane & 15);
    const int rsel = lane >> 4;
    const float4 b2v = *reinterpret_cast<const float4*>(&b2s[nb + cl]);
    const int xw = ((g >> 2) & 1) << 2;

    #pragma unroll
    for (int mt = 0; mt < 2; mt++) {
        #pragma unroll
        for (int nt = 0; nt < 8; nt++) {
            int c = (nt * 8 + 2 * tig) ^ xw;
            *reinterpret_cast<float2*>(&stg[g * STG_STRIDE + c]) =
                make_float2(acc[mt][nt][0], acc[mt][nt][1]);
            *reinterpret_cast<float2*>(&stg[(g + 8) * STG_STRIDE + c]) =
                make_float2(acc[mt][nt][2], acc[mt][nt][3]);
        }
        __syncwarp();
        #pragma unroll
        for (int rr = 0; rr < 8; rr++) {
            int r = rr * 2 + rsel;
            int xorv = ((r >> 2) & 1) << 2;
            float4 v = *reinterpret_cast<const float4*>(
                &stg[r * STG_STRIDE + (cl ^ xorv)]);
            float a2r = a2s[mb + mt * 16 + r];
            float4 o;
            o.x = -fast_sqrt(fmaxf(fmaf(-2.0f, v.x, a2r + b2v.x), 0.0f));
            o.y = -fast_sqrt(fmaxf(fmaf(-2.0f, v.y, a2r + b2v.y), 0.0f));
            o.z = -fast_sqrt(fmaxf(fmaf(-2.0f, v.z, a2r + b2v.z), 0.0f));
            o.w = -fast_sqrt(fmaxf(fmaf(-2.0f, v.w, a2r + b2v.w), 0.0f));
            *reinterpret_cast<float4*>(
                &out[(size_t)(row0 + mb + mt * 16 + r) * M + (col0 + nb + cl)])
                = o;
        }
        __syncwarp();
    }
}

extern "C" void kernel_launch(void* const* d_in, const int* in_sizes, int n_in,
                              void* d_out, int out_size) {
    const float* A = (const float*)d_in[0];   // z_anc [N,128]
    const float* B = (const float*)d_in[1];   // z_pos_neg [M,128]
    float* out = (float*)d_out;

    const int N = in_sizes[0] / DDIM;
    const int M = in_sizes[1] / DDIM;

    // First call is the (non-captured) correctness run; capture-safe.
    static bool attr_ok = [] {
        cudaFuncSetAttribute(dist_mma_kernel,
                             cudaFuncAttributeMaxDynamicSharedMemorySize,
                             SMEM_BYTES);
        return true;
    }();
    (void)attr_ok;

    int totalRows = N + M;
    prep_kernel<<<(totalRows + 7) / 8, 256>>>(A, B, N, M);

    dim3 grid(M / TN, N / TM);
    dist_mma_kernel<<<grid, 256, SMEM_BYTES>>>(out, N, M);
}